// round 8
// baseline (speedup 1.0000x reference)
#include <cuda_runtime.h>
#include <cuda_fp16.h>

#define BATCH   256
#define IN_DIM  1024
#define WIDTH   64000
#define KOUT    10
#define GROUP   (WIDTH / KOUT)   // 6400
#define NS      160              // splits per group for fused layer3+reduce
#define JS      (GROUP / NS)     // 40 neurons per block
#define L3WARPS 8
#define JW      (JS / L3WARPS)   // 5 neurons per warp
#define LGRID   592              // persistent layer kernel blocks (4/SM)
#define NPAIR   (WIDTH / 2)      // 32000 neuron-pairs per layer

// Scratch — fp16 activations, [neuron][batch] layout, 16B-aligned
__device__ __align__(256) __half g_xT[IN_DIM * BATCH];     // 0.5 MB
__device__ __align__(256) __half g_bufA[WIDTH * BATCH];    // 32.8 MB
__device__ __align__(256) __half g_bufB[WIDTH * BATCH];    // 32.8 MB
__device__ float4 g_coef[3 * WIDTH];                       // 3 MB
__device__ float  g_part[KOUT * NS * BATCH];               // 1.6 MB

// ---------------------------------------------------------------------------
__device__ __forceinline__ unsigned long long mk_policy() {
    unsigned long long p;
    asm("createpolicy.fractional.L2::evict_last.b64 %0, 0.875;" : "=l"(p));
    return p;
}
__device__ __forceinline__ uint4 ldg_el(const uint4* a, unsigned long long pol) {
    uint4 r;
    asm volatile("ld.global.L2::cache_hint.v4.u32 {%0,%1,%2,%3}, [%4], %5;"
                 : "=r"(r.x), "=r"(r.y), "=r"(r.z), "=r"(r.w)
                 : "l"(a), "l"(pol));
    return r;
}
__device__ __forceinline__ void stg_el(uint4* a, uint4 v, unsigned long long pol) {
    asm volatile("st.global.L2::cache_hint.v4.u32 [%0], {%1,%2,%3,%4}, %5;"
                 :: "l"(a), "r"(v.x), "r"(v.y), "r"(v.z), "r"(v.w), "l"(pol)
                 : "memory");
}

// ---------------------------------------------------------------------------
// Fused prologue: blocks [0,256) transpose x -> xT fp16; rest compute coefs.
__global__ __launch_bounds__(256)
void k_pre(const float* __restrict__ x,
           const float* __restrict__ w1,
           const float* __restrict__ w2,
           const float* __restrict__ w3) {
    if (blockIdx.x < 256) {
        __shared__ float tile[32][33];
        int d0 = (blockIdx.x & 31) * 32;
        int b0 = (blockIdx.x >> 5) * 32;
        int tx = threadIdx.x & 31;
        int ty = threadIdx.x >> 5;
        #pragma unroll
        for (int r = 0; r < 4; r++)
            tile[ty + r * 8][tx] =
                x[(size_t)(b0 + ty + r * 8) * IN_DIM + d0 + tx];
        __syncthreads();
        #pragma unroll
        for (int r = 0; r < 4; r++)
            g_xT[(size_t)(d0 + ty + r * 8) * BATCH + b0 + tx] =
                __float2half_rn(tile[tx][ty + r * 8]);
        return;
    }

    int tid = (blockIdx.x - 256) * blockDim.x + threadIdx.x;
    if (tid >= 3 * WIDTH) return;
    int layer = tid / WIDTH;
    int n     = tid - layer * WIDTH;
    const float* w = (layer == 0) ? w1 : (layer == 1) ? w2 : w3;
    w += (size_t)n * 16;

    float v[16];
    float m = -1e30f;
    #pragma unroll
    for (int i = 0; i < 16; i++) { v[i] = w[i]; m = fmaxf(m, v[i]); }
    float s = 0.f;
    #pragma unroll
    for (int i = 0; i < 16; i++) { v[i] = __expf(v[i] - m); s += v[i]; }
    float inv = 1.0f / s;
    #pragma unroll
    for (int i = 0; i < 16; i++) v[i] *= inv;

    float c0 = v[8]+v[9]+v[10]+v[11]+v[12]+v[13]+v[14]+v[15];
    float c1 = v[2]+v[3]+v[6]+v[7] - v[8]-v[9]-v[12]-v[13];
    float c2 = v[4]+v[5]+v[6]+v[7] - v[8]-v[9]-v[10]-v[11];
    float c3 = v[1] - v[2] - v[4] - 2.f*v[6] - v[7]
             + v[8] + 2.f*v[9] + v[11] + v[13] - v[14];
    g_coef[tid] = make_float4(c0, c1, c2, c3);
}

// ---------------------------------------------------------------------------
__device__ __forceinline__ __half2 gate_h2(float4 c, __half2 ah, __half2 bh) {
    float2 a = __half22float2(ah);
    float2 b = __half22float2(bh);
    float rx = fmaf(c.w * a.x, b.x, fmaf(c.y, a.x, fmaf(c.z, b.x, c.x)));
    float ry = fmaf(c.w * a.y, b.y, fmaf(c.y, a.y, fmaf(c.z, b.y, c.x)));
    return __floats2half2_rn(rx, ry);
}

__device__ __forceinline__ uint4 gate_u4(float4 c, uint4 av, uint4 bv) {
    uint4 r;
    ((__half2*)&r)[0] = gate_h2(c, ((__half2*)&av)[0], ((__half2*)&bv)[0]);
    ((__half2*)&r)[1] = gate_h2(c, ((__half2*)&av)[1], ((__half2*)&bv)[1]);
    ((__half2*)&r)[2] = gate_h2(c, ((__half2*)&av)[2], ((__half2*)&bv)[2]);
    ((__half2*)&r)[3] = gate_h2(c, ((__half2*)&av)[3], ((__half2*)&bv)[3]);
    return r;
}

// ---------------------------------------------------------------------------
// Persistent pipelined logic layer. Warp grid-strides over neuron-pairs;
// next pair's index loads + gathers issue before computing current pair.
__global__ __launch_bounds__(256)
void k_layer(int srcSel, int dstSel, int coefOff,
             const int* __restrict__ ia, const int* __restrict__ ib) {
    int wid  = (blockIdx.x << 3) + (threadIdx.x >> 5);
    int lane = threadIdx.x & 31;
    int W    = gridDim.x << 3;

    const __half* src = (srcSel == 0) ? g_xT : (srcSel == 1) ? g_bufA : g_bufB;
    __half*       dst = (dstSel == 1) ? g_bufA : g_bufB;
    unsigned long long pol = mk_policy();

    int t = wid;                    // t < NPAIR guaranteed (W << NPAIR)
    float4 c0, c1;
    uint4 a0, b0, a1, b1;
    {
        int n0 = t * 2;
        int A0 = __ldg(ia + n0), B0 = __ldg(ib + n0);
        int A1 = __ldg(ia + n0 + 1), B1 = __ldg(ib + n0 + 1);
        c0 = __ldg(&g_coef[coefOff + n0]);
        c1 = __ldg(&g_coef[coefOff + n0 + 1]);
        a0 = ldg_el((const uint4*)(src + (size_t)A0 * BATCH) + lane, pol);
        b0 = ldg_el((const uint4*)(src + (size_t)B0 * BATCH) + lane, pol);
        a1 = ldg_el((const uint4*)(src + (size_t)A1 * BATCH) + lane, pol);
        b1 = ldg_el((const uint4*)(src + (size_t)B1 * BATCH) + lane, pol);
    }

    while (true) {
        int cn = t * 2;
        int tn = t + W;
        uint4 pa0 = a0, pb0 = b0, pa1 = a1, pb1 = b1;
        float4 pc0 = c0, pc1 = c1;

        if (tn < NPAIR) {           // issue next iteration's loads first
            int n0 = tn * 2;
            int A0 = __ldg(ia + n0), B0 = __ldg(ib + n0);
            int A1 = __ldg(ia + n0 + 1), B1 = __ldg(ib + n0 + 1);
            c0 = __ldg(&g_coef[coefOff + n0]);
            c1 = __ldg(&g_coef[coefOff + n0 + 1]);
            a0 = ldg_el((const uint4*)(src + (size_t)A0 * BATCH) + lane, pol);
            b0 = ldg_el((const uint4*)(src + (size_t)B0 * BATCH) + lane, pol);
            a1 = ldg_el((const uint4*)(src + (size_t)A1 * BATCH) + lane, pol);
            b1 = ldg_el((const uint4*)(src + (size_t)B1 * BATCH) + lane, pol);
        }

        stg_el((uint4*)(dst + (size_t)cn * BATCH) + lane,
               gate_u4(pc0, pa0, pb0), pol);
        stg_el((uint4*)(dst + (size_t)(cn + 1) * BATCH) + lane,
               gate_u4(pc1, pa1, pb1), pol);

        if (tn >= NPAIR) break;
        t = tn;
    }
}

// ---------------------------------------------------------------------------
// Fused layer-3 + partial group sum. JW=5 neurons/warp, ALL 10 gathers issued
// back-to-back (single latency exposure), fp32 accumulation, smem reduce.
__global__ __launch_bounds__(256)
void k_layer3_reduce(const int* __restrict__ ia, const int* __restrict__ ib) {
    int k    = blockIdx.x;            // 0..9
    int s    = blockIdx.y;            // 0..NS-1
    int w    = threadIdx.x >> 5;      // 0..7
    int lane = threadIdx.x & 31;

    const __half* src = g_bufB;       // layer-2 output
    unsigned long long pol = mk_policy();
    int n0 = k * GROUP + s * JS + w * JW;

    // Batch all index loads
    int A[JW], B[JW];
    #pragma unroll
    for (int j = 0; j < JW; j++) {
        A[j] = __ldg(ia + n0 + j);
        B[j] = __ldg(ib + n0 + j);
    }
    // Issue all 10 gathers back-to-back
    uint4 av[JW], bv[JW];
    #pragma unroll
    for (int j = 0; j < JW; j++) {
        av[j] = ldg_el((const uint4*)(src + (size_t)A[j] * BATCH) + lane, pol);
        bv[j] = ldg_el((const uint4*)(src + (size_t)B[j] * BATCH) + lane, pol);
    }

    float acc[8] = {0.f,0.f,0.f,0.f,0.f,0.f,0.f,0.f};
    #pragma unroll
    for (int j = 0; j < JW; j++) {
        float4 c = __ldg(&g_coef[2 * WIDTH + n0 + j]);
        #pragma unroll
        for (int h = 0; h < 4; h++) {
            float2 a = __half22float2(((__half2*)&av[j])[h]);
            float2 b = __half22float2(((__half2*)&bv[j])[h]);
            acc[2*h]   += fmaf(c.w * a.x, b.x, fmaf(c.y, a.x, fmaf(c.z, b.x, c.x)));
            acc[2*h+1] += fmaf(c.w * a.y, b.y, fmaf(c.y, a.y, fmaf(c.z, b.y, c.x)));
        }
    }

    __shared__ float part[L3WARPS][BATCH];
    #pragma unroll
    for (int i = 0; i < 8; i++) part[w][lane * 8 + i] = acc[i];
    __syncthreads();

    int col = threadIdx.x;
    float v = 0.f;
    #pragma unroll
    for (int i = 0; i < L3WARPS; i++) v += part[i][col];
    g_part[(size_t)(k * NS + s) * BATCH + col] = v;
}

// Stage-2: sum NS partials, scale by 1/TAU, write out[b][k]
__global__ void k_freduce(float* __restrict__ out) {
    int k = blockIdx.x;   // 0..9
    int b = threadIdx.x;  // 0..255
    float acc = 0.f;
    #pragma unroll 8
    for (int s = 0; s < NS; s++)
        acc += g_part[(size_t)(k * NS + s) * BATCH + b];
    out[b * KOUT + k] = acc * (1.0f / 30.0f);
}

// ---------------------------------------------------------------------------
extern "C" void kernel_launch(void* const* d_in, const int* in_sizes, int n_in,
                              void* d_out, int out_size) {
    const float* x   = (const float*)d_in[0];
    const float* w1  = (const float*)d_in[1];
    const float* w2  = (const float*)d_in[2];
    const float* w3  = (const float*)d_in[3];
    const int*   ia1 = (const int*)d_in[4];
    const int*   ib1 = (const int*)d_in[5];
    const int*   ia2 = (const int*)d_in[6];
    const int*   ib2 = (const int*)d_in[7];
    const int*   ia3 = (const int*)d_in[8];
    const int*   ib3 = (const int*)d_in[9];
    float* out = (float*)d_out;

    k_pre<<<256 + (3 * WIDTH + 255) / 256, 256>>>(x, w1, w2, w3);

    k_layer<<<LGRID, 256>>>(0, 1, 0,     ia1, ib1);  // xT   -> bufA
    k_layer<<<LGRID, 256>>>(1, 2, WIDTH, ia2, ib2);  // bufA -> bufB

    k_layer3_reduce<<<dim3(KOUT, NS), 256>>>(ia3, ib3);  // bufB -> partials
    k_freduce<<<KOUT, BATCH>>>(out);
}

// round 9
// speedup vs baseline: 1.2237x; 1.2237x over previous
#include <cuda_runtime.h>
#include <cuda_fp16.h>

#define BATCH   256
#define IN_DIM  1024
#define WIDTH   64000
#define KOUT    10
#define GROUP   (WIDTH / KOUT)   // 6400
#define NS      80               // splits per group for fused layer3+reduce
#define JS      (GROUP / NS)     // 80 neurons per block
#define L3WARPS 8
#define JW      (JS / L3WARPS)   // 10 neurons per warp

// Activations stored as unorm8 (v = round(255*a)), [neuron][batch] layout.
__device__ __align__(256) unsigned char g_xT[IN_DIM * BATCH];   // 256 KB
__device__ __align__(256) unsigned char g_bufA[WIDTH * BATCH];  // 16.4 MB
__device__ __align__(256) unsigned char g_bufB[WIDTH * BATCH];  // 16.4 MB
// Per-neuron byte-domain gate constants (k0,k1,k2,k3) as 4 packed halfs:
//   out_byte = k0 + k1*a' + k2*b' + k3*a'*b',  a',b' in [0,255]
__device__ uint2  g_coefh[3 * WIDTH];                           // 1.5 MB
__device__ float  g_part[KOUT * NS * BATCH];                    // 800 KB

// ---------------------------------------------------------------------------
__device__ __forceinline__ __half2 h2const(unsigned short bits) {
    return __half2half2(__ushort_as_half(bits));
}
// Decode 4 unorm8 bytes (one u32) -> two half2 holding the byte VALUES [0,255].
// Trick: prmt builds 0x64??  (half bits 0x6400|v == 1024+v), subtract 1024.
__device__ __forceinline__ void decode4(unsigned int v, __half2& lo, __half2& hi) {
    const unsigned int m = 0x64646464u;
    const __half2 h1024 = h2const(0x6400);
    unsigned int t0, t1;
    asm("prmt.b32 %0, %1, %2, 0x4140;" : "=r"(t0) : "r"(v), "r"(m));
    asm("prmt.b32 %0, %1, %2, 0x4342;" : "=r"(t1) : "r"(v), "r"(m));
    lo = __hsub2(*reinterpret_cast<__half2*>(&t0), h1024);
    hi = __hsub2(*reinterpret_cast<__half2*>(&t1), h1024);
}
// Gate in byte domain (half2 SIMD)
__device__ __forceinline__ __half2 gate2(__half2 a, __half2 b,
                                         __half2 k0, __half2 k1,
                                         __half2 k2, __half2 k3) {
    __half2 t = __hfma2(k1, a, k0);
    t = __hfma2(k2, b, t);
    return __hfma2(k3, __hmul2(a, b), t);
}
// Encode two half2 byte-values -> 4 packed unorm8 (round-to-nearest + clamp)
__device__ __forceinline__ unsigned int encode4(__half2 e0, __half2 e1) {
    const __half2 h1024 = h2const(0x6400);   // 1024.0
    const __half2 h1279 = h2const(0x64FF);   // 1279.0
    e0 = __hmin2(__hmax2(__hadd2(e0, h1024), h1024), h1279);
    e1 = __hmin2(__hmax2(__hadd2(e1, h1024), h1024), h1279);
    unsigned int u0 = *reinterpret_cast<unsigned int*>(&e0);
    unsigned int u1 = *reinterpret_cast<unsigned int*>(&e1);
    unsigned int r;
    asm("prmt.b32 %0, %1, %2, 0x6420;" : "=r"(r) : "r"(u0), "r"(u1));
    return r;
}
// Unpack per-neuron constants
__device__ __forceinline__ void coef_h2(uint2 c, __half2& k0, __half2& k1,
                                        __half2& k2, __half2& k3) {
    k0 = h2const((unsigned short)(c.x & 0xFFFF));
    k1 = h2const((unsigned short)(c.x >> 16));
    k2 = h2const((unsigned short)(c.y & 0xFFFF));
    k3 = h2const((unsigned short)(c.y >> 16));
}

// ---------------------------------------------------------------------------
// Fused prologue: blocks [0,256) transpose+quantize x; rest compute constants.
__global__ __launch_bounds__(256)
void k_pre(const float* __restrict__ x,
           const float* __restrict__ w1,
           const float* __restrict__ w2,
           const float* __restrict__ w3) {
    if (blockIdx.x < 256) {
        __shared__ float tile[32][33];
        int d0 = (blockIdx.x & 31) * 32;
        int b0 = (blockIdx.x >> 5) * 32;
        int tx = threadIdx.x & 31;
        int ty = threadIdx.x >> 5;
        #pragma unroll
        for (int r = 0; r < 4; r++)
            tile[ty + r * 8][tx] =
                x[(size_t)(b0 + ty + r * 8) * IN_DIM + d0 + tx];
        __syncthreads();
        #pragma unroll
        for (int r = 0; r < 4; r++) {
            float v = tile[tx][ty + r * 8];
            g_xT[(size_t)(d0 + ty + r * 8) * BATCH + b0 + tx] =
                (unsigned char)__float2uint_rn(__saturatef(v) * 255.f);
        }
        return;
    }

    int tid = (blockIdx.x - 256) * blockDim.x + threadIdx.x;
    if (tid >= 3 * WIDTH) return;
    int layer = tid / WIDTH;
    int n     = tid - layer * WIDTH;
    const float* w = (layer == 0) ? w1 : (layer == 1) ? w2 : w3;
    w += (size_t)n * 16;

    float v[16];
    float m = -1e30f;
    #pragma unroll
    for (int i = 0; i < 16; i++) { v[i] = w[i]; m = fmaxf(m, v[i]); }
    float s = 0.f;
    #pragma unroll
    for (int i = 0; i < 16; i++) { v[i] = __expf(v[i] - m); s += v[i]; }
    float inv = 1.0f / s;
    #pragma unroll
    for (int i = 0; i < 16; i++) v[i] *= inv;

    float c0 = v[8]+v[9]+v[10]+v[11]+v[12]+v[13]+v[14]+v[15];
    float c1 = v[2]+v[3]+v[6]+v[7] - v[8]-v[9]-v[12]-v[13];
    float c2 = v[4]+v[5]+v[6]+v[7] - v[8]-v[9]-v[10]-v[11];
    float c3 = v[1] - v[2] - v[4] - 2.f*v[6] - v[7]
             + v[8] + 2.f*v[9] + v[11] + v[13] - v[14];

    // Byte-domain constants
    __half k0 = __float2half_rn(255.f * c0);
    __half k1 = __float2half_rn(c1);
    __half k2 = __float2half_rn(c2);
    __half k3 = __float2half_rn(c3 * (1.f / 255.f));
    uint2 pk;
    pk.x = (unsigned int)__half_as_ushort(k0) |
           ((unsigned int)__half_as_ushort(k1) << 16);
    pk.y = (unsigned int)__half_as_ushort(k2) |
           ((unsigned int)__half_as_ushort(k3) << 16);
    g_coefh[tid] = pk;
}

// ---------------------------------------------------------------------------
// One logic layer, unorm8 in/out, TWO neurons per warp.
// Row = 256 bytes; lane loads uint2 (8B) -> warp covers one row per load.
__global__ __launch_bounds__(256)
void k_layer(int srcSel, int dstSel, int coefOff,
             const int* __restrict__ ia, const int* __restrict__ ib) {
    int warp = blockIdx.x * 8 + (threadIdx.x >> 5);
    int n0   = warp * 2;
    int n1   = n0 + 1;
    int lane = threadIdx.x & 31;

    const unsigned char* src = (srcSel == 0) ? g_xT
                             : (srcSel == 1) ? g_bufA : g_bufB;
    unsigned char* dst = (dstSel == 1) ? g_bufA : g_bufB;

    int A0 = __ldg(ia + n0), B0 = __ldg(ib + n0);
    int A1 = __ldg(ia + n1), B1 = __ldg(ib + n1);
    uint2 pc0 = g_coefh[coefOff + n0];
    uint2 pc1 = g_coefh[coefOff + n1];

    // 4 independent 8B gathers in flight per lane
    uint2 av0 = __ldg((const uint2*)(src + (size_t)A0 * BATCH) + lane);
    uint2 bv0 = __ldg((const uint2*)(src + (size_t)B0 * BATCH) + lane);
    uint2 av1 = __ldg((const uint2*)(src + (size_t)A1 * BATCH) + lane);
    uint2 bv1 = __ldg((const uint2*)(src + (size_t)B1 * BATCH) + lane);

    __half2 k0, k1, k2, k3;
    {
        coef_h2(pc0, k0, k1, k2, k3);
        __half2 aL, aH, bL, bH, a2L, a2H, b2L, b2H;
        decode4(av0.x, aL, aH);  decode4(bv0.x, bL, bH);
        decode4(av0.y, a2L, a2H); decode4(bv0.y, b2L, b2H);
        uint2 r;
        r.x = encode4(gate2(aL, bL, k0, k1, k2, k3),
                      gate2(aH, bH, k0, k1, k2, k3));
        r.y = encode4(gate2(a2L, b2L, k0, k1, k2, k3),
                      gate2(a2H, b2H, k0, k1, k2, k3));
        ((uint2*)(dst + (size_t)n0 * BATCH))[lane] = r;
    }
    {
        coef_h2(pc1, k0, k1, k2, k3);
        __half2 aL, aH, bL, bH, a2L, a2H, b2L, b2H;
        decode4(av1.x, aL, aH);  decode4(bv1.x, bL, bH);
        decode4(av1.y, a2L, a2H); decode4(bv1.y, b2L, b2H);
        uint2 r;
        r.x = encode4(gate2(aL, bL, k0, k1, k2, k3),
                      gate2(aH, bH, k0, k1, k2, k3));
        r.y = encode4(gate2(a2L, b2L, k0, k1, k2, k3),
                      gate2(a2H, b2H, k0, k1, k2, k3));
        ((uint2*)(dst + (size_t)n1 * BATCH))[lane] = r;
    }
}

// ---------------------------------------------------------------------------
// Fused layer-3 + partial group sum. 8 warps/block, JW=10 neurons per warp,
// gate values accumulated in fp32 byte-domain (no quantization of layer 3).
__global__ __launch_bounds__(256)
void k_layer3_reduce(const int* __restrict__ ia, const int* __restrict__ ib) {
    int k    = blockIdx.x;            // 0..9
    int s    = blockIdx.y;            // 0..NS-1
    int w    = threadIdx.x >> 5;      // 0..7
    int lane = threadIdx.x & 31;

    const unsigned char* src = g_bufB;   // layer-2 output
    int n0 = k * GROUP + s * JS + w * JW;

    float acc[8] = {0.f,0.f,0.f,0.f,0.f,0.f,0.f,0.f};

    #pragma unroll 2
    for (int j = 0; j < JW; j++) {
        int n = n0 + j;
        int A = __ldg(ia + n);
        int B = __ldg(ib + n);
        uint2 pc = g_coefh[2 * WIDTH + n];
        uint2 av = __ldg((const uint2*)(src + (size_t)A * BATCH) + lane);
        uint2 bv = __ldg((const uint2*)(src + (size_t)B * BATCH) + lane);

        __half2 k0, k1, k2, k3;
        coef_h2(pc, k0, k1, k2, k3);
        __half2 aL, aH, bL, bH, a2L, a2H, b2L, b2H;
        decode4(av.x, aL, aH);   decode4(bv.x, bL, bH);
        decode4(av.y, a2L, a2H); decode4(bv.y, b2L, b2H);

        float2 r0 = __half22float2(gate2(aL,  bL,  k0, k1, k2, k3));
        float2 r1 = __half22float2(gate2(aH,  bH,  k0, k1, k2, k3));
        float2 r2 = __half22float2(gate2(a2L, b2L, k0, k1, k2, k3));
        float2 r3 = __half22float2(gate2(a2H, b2H, k0, k1, k2, k3));
        acc[0] += r0.x; acc[1] += r0.y;
        acc[2] += r1.x; acc[3] += r1.y;
        acc[4] += r2.x; acc[5] += r2.y;
        acc[6] += r3.x; acc[7] += r3.y;
    }

    __shared__ float part[L3WARPS][BATCH];
    #pragma unroll
    for (int i = 0; i < 8; i++) part[w][lane * 8 + i] = acc[i];
    __syncthreads();

    int col = threadIdx.x;
    float v = 0.f;
    #pragma unroll
    for (int i = 0; i < L3WARPS; i++) v += part[i][col];
    g_part[(size_t)(k * NS + s) * BATCH + col] = v;
}

// Stage-2: sum NS partials, scale by 1/(255*TAU), write out[b][k]
__global__ void k_freduce(float* __restrict__ out) {
    int k = blockIdx.x;   // 0..9
    int b = threadIdx.x;  // 0..255
    float acc = 0.f;
    #pragma unroll 8
    for (int s = 0; s < NS; s++)
        acc += g_part[(size_t)(k * NS + s) * BATCH + b];
    out[b * KOUT + k] = acc * (1.0f / (255.0f * 30.0f));
}

// ---------------------------------------------------------------------------
extern "C" void kernel_launch(void* const* d_in, const int* in_sizes, int n_in,
                              void* d_out, int out_size) {
    const float* x   = (const float*)d_in[0];
    const float* w1  = (const float*)d_in[1];
    const float* w2  = (const float*)d_in[2];
    const float* w3  = (const float*)d_in[3];
    const int*   ia1 = (const int*)d_in[4];
    const int*   ib1 = (const int*)d_in[5];
    const int*   ia2 = (const int*)d_in[6];
    const int*   ib2 = (const int*)d_in[7];
    const int*   ia3 = (const int*)d_in[8];
    const int*   ib3 = (const int*)d_in[9];
    float* out = (float*)d_out;

    k_pre<<<256 + (3 * WIDTH + 255) / 256, 256>>>(x, w1, w2, w3);

    k_layer<<<WIDTH / 16, 256>>>(0, 1, 0,     ia1, ib1);  // xT   -> bufA
    k_layer<<<WIDTH / 16, 256>>>(1, 2, WIDTH, ia2, ib2);  // bufA -> bufB

    k_layer3_reduce<<<dim3(KOUT, NS), 256>>>(ia3, ib3);   // bufB -> partials
    k_freduce<<<KOUT, BATCH>>>(out);
}

// round 11
// speedup vs baseline: 1.2292x; 1.0046x over previous
#include <cuda_runtime.h>
#include <cuda_fp16.h>

#define BATCH   256
#define IN_DIM  1024
#define WIDTH   64000
#define KOUT    10
#define GROUP   (WIDTH / KOUT)   // 6400
#define NS      80               // splits per group for fused layer3+reduce
#define JS      (GROUP / NS)     // 80 neurons per block
#define L3WARPS 8
#define JW      (JS / L3WARPS)   // 10 neurons per warp

// fp16 activations (value domain), [neuron][batch] layout, 16B-aligned rows
__device__ __align__(256) __half g_xT[IN_DIM * BATCH];     // 0.5 MB
__device__ __align__(256) __half g_bufA[WIDTH * BATCH];    // 32.8 MB
__device__ __align__(256) __half g_bufB[WIDTH * BATCH];    // 32.8 MB
// Per-neuron coefficients pre-broadcast: uint4 = {k0k0, k1k1, k2k2, k3k3}
__device__ uint4  g_coefh4[3 * WIDTH];                     // 3 MB
__device__ float  g_part[KOUT * NS * BATCH];               // 800 KB

// ---------------------------------------------------------------------------
__device__ __forceinline__ __half2 u2h2(unsigned int u) {
    return *reinterpret_cast<__half2*>(&u);
}
// gate: k0 + k1*a + k2*b + k3*(a*b), all half2 SIMD — 4 ops
__device__ __forceinline__ __half2 gate2(__half2 a, __half2 b,
                                         __half2 k0, __half2 k1,
                                         __half2 k2, __half2 k3) {
    __half2 t = __hfma2(k1, a, k0);
    t = __hfma2(k2, b, t);
    return __hfma2(k3, __hmul2(a, b), t);
}
// full 8-half gate on uint4 registers
__device__ __forceinline__ uint4 gate_u4(uint4 pc, uint4 av, uint4 bv) {
    __half2 k0 = u2h2(pc.x), k1 = u2h2(pc.y), k2 = u2h2(pc.z), k3 = u2h2(pc.w);
    uint4 r;
    ((__half2*)&r)[0] = gate2(((__half2*)&av)[0], ((__half2*)&bv)[0], k0, k1, k2, k3);
    ((__half2*)&r)[1] = gate2(((__half2*)&av)[1], ((__half2*)&bv)[1], k0, k1, k2, k3);
    ((__half2*)&r)[2] = gate2(((__half2*)&av)[2], ((__half2*)&bv)[2], k0, k1, k2, k3);
    ((__half2*)&r)[3] = gate2(((__half2*)&av)[3], ((__half2*)&bv)[3], k0, k1, k2, k3);
    return r;
}

// ---------------------------------------------------------------------------
// Fused prologue: blocks [0,256) transpose x -> xT fp16; rest compute coefs.
__global__ __launch_bounds__(256)
void k_pre(const float* __restrict__ x,
           const float* __restrict__ w1,
           const float* __restrict__ w2,
           const float* __restrict__ w3) {
    if (blockIdx.x < 256) {
        __shared__ float tile[32][33];
        int d0 = (blockIdx.x & 31) * 32;
        int b0 = (blockIdx.x >> 5) * 32;
        int tx = threadIdx.x & 31;
        int ty = threadIdx.x >> 5;
        #pragma unroll
        for (int r = 0; r < 4; r++)
            tile[ty + r * 8][tx] =
                x[(size_t)(b0 + ty + r * 8) * IN_DIM + d0 + tx];
        __syncthreads();
        #pragma unroll
        for (int r = 0; r < 4; r++)
            g_xT[(size_t)(d0 + ty + r * 8) * BATCH + b0 + tx] =
                __float2half_rn(tile[tx][ty + r * 8]);
        return;
    }

    int tid = (blockIdx.x - 256) * blockDim.x + threadIdx.x;
    if (tid >= 3 * WIDTH) return;
    int layer = tid / WIDTH;
    int n     = tid - layer * WIDTH;
    const float* w = (layer == 0) ? w1 : (layer == 1) ? w2 : w3;
    w += (size_t)n * 16;

    float v[16];
    float m = -1e30f;
    #pragma unroll
    for (int i = 0; i < 16; i++) { v[i] = w[i]; m = fmaxf(m, v[i]); }
    float s = 0.f;
    #pragma unroll
    for (int i = 0; i < 16; i++) { v[i] = __expf(v[i] - m); s += v[i]; }
    float inv = __fdividef(1.0f, s);
    #pragma unroll
    for (int i = 0; i < 16; i++) v[i] *= inv;

    float c0 = v[8]+v[9]+v[10]+v[11]+v[12]+v[13]+v[14]+v[15];
    float c1 = v[2]+v[3]+v[6]+v[7] - v[8]-v[9]-v[12]-v[13];
    float c2 = v[4]+v[5]+v[6]+v[7] - v[8]-v[9]-v[10]-v[11];
    float c3 = v[1] - v[2] - v[4] - 2.f*v[6] - v[7]
             + v[8] + 2.f*v[9] + v[11] + v[13] - v[14];

    __half2 h0 = __half2half2(__float2half_rn(c0));
    __half2 h1 = __half2half2(__float2half_rn(c1));
    __half2 h2 = __half2half2(__float2half_rn(c2));
    __half2 h3 = __half2half2(__float2half_rn(c3));
    uint4 pk;
    pk.x = *reinterpret_cast<unsigned int*>(&h0);
    pk.y = *reinterpret_cast<unsigned int*>(&h1);
    pk.z = *reinterpret_cast<unsigned int*>(&h2);
    pk.w = *reinterpret_cast<unsigned int*>(&h3);
    g_coefh4[tid] = pk;
}

// ---------------------------------------------------------------------------
// One logic layer, fp16 in/out, TWO neurons per warp, native half2 math.
// Row = 512B; lane loads uint4 (16B) -> warp covers one row per load.
__global__ __launch_bounds__(256)
void k_layer(int srcSel, int dstSel, int coefOff,
             const int* __restrict__ ia, const int* __restrict__ ib) {
    int warp = blockIdx.x * 8 + (threadIdx.x >> 5);
    int n0   = warp * 2;
    int n1   = n0 + 1;
    int lane = threadIdx.x & 31;

    const __half* src = (srcSel == 0) ? g_xT : (srcSel == 1) ? g_bufA : g_bufB;
    __half*       dst = (dstSel == 1) ? g_bufA : g_bufB;

    int A0 = __ldg(ia + n0), B0 = __ldg(ib + n0);
    int A1 = __ldg(ia + n1), B1 = __ldg(ib + n1);
    uint4 pc0 = __ldg(&g_coefh4[coefOff + n0]);
    uint4 pc1 = __ldg(&g_coefh4[coefOff + n1]);

    // 4 independent 16B gathers in flight per lane
    uint4 a0 = __ldg((const uint4*)(src + (size_t)A0 * BATCH) + lane);
    uint4 b0 = __ldg((const uint4*)(src + (size_t)B0 * BATCH) + lane);
    uint4 a1 = __ldg((const uint4*)(src + (size_t)A1 * BATCH) + lane);
    uint4 b1 = __ldg((const uint4*)(src + (size_t)B1 * BATCH) + lane);

    ((uint4*)(dst + (size_t)n0 * BATCH))[lane] = gate_u4(pc0, a0, b0);
    ((uint4*)(dst + (size_t)n1 * BATCH))[lane] = gate_u4(pc1, a1, b1);
}

// ---------------------------------------------------------------------------
// Fused layer-3 + partial group sum. 8 warps/block, JW=10 neurons per warp.
// Gates accumulated in half2 (sum <= 10, safe), one cvt to fp32 at the end.
__global__ __launch_bounds__(256)
void k_layer3_reduce(const int* __restrict__ ia, const int* __restrict__ ib) {
    int k    = blockIdx.x;            // 0..9
    int s    = blockIdx.y;            // 0..NS-1
    int w    = threadIdx.x >> 5;      // 0..7
    int lane = threadIdx.x & 31;

    const __half* src = g_bufB;       // layer-2 output
    int n0 = k * GROUP + s * JS + w * JW;

    __half2 acc[4];
    #pragma unroll
    for (int h = 0; h < 4; h++) acc[h] = __half2half2(__ushort_as_half(0));

    #pragma unroll 2
    for (int j = 0; j < JW; j++) {
        int n = n0 + j;
        int A = __ldg(ia + n);
        int B = __ldg(ib + n);
        uint4 pc = __ldg(&g_coefh4[2 * WIDTH + n]);
        uint4 av = __ldg((const uint4*)(src + (size_t)A * BATCH) + lane);
        uint4 bv = __ldg((const uint4*)(src + (size_t)B * BATCH) + lane);

        __half2 k0 = u2h2(pc.x), k1 = u2h2(pc.y), k2 = u2h2(pc.z), k3 = u2h2(pc.w);
        #pragma unroll
        for (int h = 0; h < 4; h++) {
            acc[h] = __hadd2(acc[h],
                gate2(((__half2*)&av)[h], ((__half2*)&bv)[h], k0, k1, k2, k3));
        }
    }

    __shared__ float part[L3WARPS][BATCH];
    #pragma unroll
    for (int h = 0; h < 4; h++) {
        float2 f = __half22float2(acc[h]);
        part[w][lane * 8 + 2 * h]     = f.x;
        part[w][lane * 8 + 2 * h + 1] = f.y;
    }
    __syncthreads();

    int col = threadIdx.x;
    float v = 0.f;
    #pragma unroll
    for (int i = 0; i < L3WARPS; i++) v += part[i][col];
    g_part[(size_t)(k * NS + s) * BATCH + col] = v;
}

// Stage-2: sum NS partials, scale by 1/TAU, write out[b][k]
__global__ void k_freduce(float* __restrict__ out) {
    int k = blockIdx.x;   // 0..9
    int b = threadIdx.x;  // 0..255
    float acc = 0.f;
    #pragma unroll 8
    for (int s = 0; s < NS; s++)
        acc += g_part[(size_t)(k * NS + s) * BATCH + b];
    out[b * KOUT + k] = acc * (1.0f / 30.0f);
}

// ---------------------------------------------------------------------------
extern "C" void kernel_launch(void* const* d_in, const int* in_sizes, int n_in,
                              void* d_out, int out_size) {
    const float* x   = (const float*)d_in[0];
    const float* w1  = (const float*)d_in[1];
    const float* w2  = (const float*)d_in[2];
    const float* w3  = (const float*)d_in[3];
    const int*   ia1 = (const int*)d_in[4];
    const int*   ib1 = (const int*)d_in[5];
    const int*   ia2 = (const int*)d_in[6];
    const int*   ib2 = (const int*)d_in[7];
    const int*   ia3 = (const int*)d_in[8];
    const int*   ib3 = (const int*)d_in[9];
    float* out = (float*)d_out;

    k_pre<<<256 + (3 * WIDTH + 255) / 256, 256>>>(x, w1, w2, w3);

    k_layer<<<WIDTH / 16, 256>>>(0, 1, 0,     ia1, ib1);  // xT   -> bufA
    k_layer<<<WIDTH / 16, 256>>>(1, 2, WIDTH, ia2, ib2);  // bufA -> bufB

    k_layer3_reduce<<<dim3(KOUT, NS), 256>>>(ia3, ib3);   // bufB -> partials
    k_freduce<<<KOUT, BATCH>>>(out);
}